// round 1
// baseline (speedup 1.0000x reference)
#include <cuda_runtime.h>

// ---------------------------------------------------------------------------
// ProbSparseAttention  B=2, L=4096, dm=128, H=8, D=16, sample_k=41
// ---------------------------------------------------------------------------

#define L      4096
#define DM     128
#define H      8
#define DH     16
#define NBH    16          // B*H
#define SK     41          // sample_k = int(log(4096)*5)
#define LOG2E  1.4426950408889634f

// Scratch (device globals; no allocation allowed)
__device__ float g_Q[NBH * L * DH];
__device__ float g_K[NBH * L * DH];
__device__ float g_V[NBH * L * DH];
__device__ float g_m[NBH * L];        // per-query score max (reference m)
__device__ float g_mean[NBH * L];     // per-key sum of exp (mean up to 1/L scale)
__device__ int   g_idx[NBH * SK];
__device__ float g_ctx[2 * L * DM];   // attention output, [B,L,H*D] layout

__device__ __forceinline__ float ex2f(float x) {
    float r;
    asm("ex2.approx.ftz.f32 %0, %1;" : "=f"(r) : "f"(x));
    return r;
}

__device__ __forceinline__ float dot16(const float4 a0, const float4 a1,
                                       const float4 a2, const float4 a3,
                                       const float4 b0, const float4 b1,
                                       const float4 b2, const float4 b3) {
    float s0 = a0.x * b0.x; s0 = fmaf(a0.y, b0.y, s0); s0 = fmaf(a0.z, b0.z, s0); s0 = fmaf(a0.w, b0.w, s0);
    float s1 = a1.x * b1.x; s1 = fmaf(a1.y, b1.y, s1); s1 = fmaf(a1.z, b1.z, s1); s1 = fmaf(a1.w, b1.w, s1);
    float s2 = a2.x * b2.x; s2 = fmaf(a2.y, b2.y, s2); s2 = fmaf(a2.z, b2.z, s2); s2 = fmaf(a2.w, b2.w, s2);
    float s3 = a3.x * b3.x; s3 = fmaf(a3.y, b3.y, s3); s3 = fmaf(a3.z, b3.z, s3); s3 = fmaf(a3.w, b3.w, s3);
    return (s0 + s1) + (s2 + s3);
}

// ---------------------------------------------------------------------------
// GEMM: C[8192,128] = A[8192,128] @ W[128,128] + bias
// HEADMAJOR: write into [B,H,L,16] layout (for Q/K/V); else row-major.
// Block: 64 rows x 128 cols, 256 threads, k staged in chunks of 32.
// ---------------------------------------------------------------------------
template <bool HEADMAJOR>
__device__ __forceinline__ void gemm_body(const float* __restrict__ A,
                                          const float* __restrict__ W,
                                          const float* __restrict__ bias,
                                          float* __restrict__ C) {
    __shared__ float sA[64][33];    // 32-wide k-chunk, padded
    __shared__ float sW[32][128];

    const int tid = threadIdx.x;
    const int tx = tid & 15;        // 16 column groups
    const int ty = tid >> 4;        // 16 row groups
    const int rowBase = blockIdx.x * 64;

    float acc[4][8];
#pragma unroll
    for (int r = 0; r < 4; r++)
#pragma unroll
        for (int c = 0; c < 8; c++) acc[r][c] = 0.0f;

    for (int kc = 0; kc < 128; kc += 32) {
        // A chunk: 64 x 32 = 512 float4
#pragma unroll
        for (int i = tid; i < 512; i += 256) {
            int r  = i >> 3;
            int c4 = i & 7;
            float4 v = *(const float4*)(A + (size_t)(rowBase + r) * DM + kc + c4 * 4);
            sA[r][c4 * 4 + 0] = v.x;
            sA[r][c4 * 4 + 1] = v.y;
            sA[r][c4 * 4 + 2] = v.z;
            sA[r][c4 * 4 + 3] = v.w;
        }
        // W chunk: 32 x 128 = 1024 float4
#pragma unroll
        for (int i = tid; i < 1024; i += 256) {
            int r  = i >> 5;
            int c4 = i & 31;
            *(float4*)(&sW[r][c4 * 4]) =
                *(const float4*)(W + (size_t)(kc + r) * DM + c4 * 4);
        }
        __syncthreads();

#pragma unroll
        for (int k = 0; k < 32; k++) {
            float a[4], b[8];
#pragma unroll
            for (int r = 0; r < 4; r++) a[r] = sA[ty * 4 + r][k];
#pragma unroll
            for (int c = 0; c < 8; c++) b[c] = sW[k][tx + 16 * c];
#pragma unroll
            for (int r = 0; r < 4; r++)
#pragma unroll
                for (int c = 0; c < 8; c++) acc[r][c] = fmaf(a[r], b[c], acc[r][c]);
        }
        __syncthreads();
    }

#pragma unroll
    for (int r = 0; r < 4; r++) {
        int row = rowBase + ty * 4 + r;
#pragma unroll
        for (int c = 0; c < 8; c++) {
            int col = tx + 16 * c;
            float val = acc[r][c] + bias[col];
            if (HEADMAJOR) {
                int b  = row >> 12;       // row / 4096
                int l  = row & (L - 1);
                int h  = col >> 4;
                int d  = col & 15;
                C[((size_t)(b * H + h) * L + l) * DH + d] = val;
            } else {
                C[(size_t)row * DM + col] = val;
            }
        }
    }
}

__global__ void __launch_bounds__(256)
qkv_gemm_kernel(const float* __restrict__ x,
                const float* __restrict__ Wq, const float* __restrict__ bq,
                const float* __restrict__ Wk, const float* __restrict__ bk,
                const float* __restrict__ Wv, const float* __restrict__ bv) {
    int which = blockIdx.y;
    const float* W    = (which == 0) ? Wq : (which == 1) ? Wk : Wv;
    const float* bias = (which == 0) ? bq : (which == 1) ? bk : bv;
    float* out        = (which == 0) ? g_Q : (which == 1) ? g_K : g_V;
    gemm_body<true>(x, W, bias, out);
}

__global__ void __launch_bounds__(256)
out_gemm_kernel(const float* __restrict__ Wo, const float* __restrict__ bo,
                float* __restrict__ out) {
    gemm_body<false>(g_ctx, Wo, bo, out);
}

// ---------------------------------------------------------------------------
// Pass A: m[bh][q] = max_k (q . k) * 0.25
// grid (8 q-tiles, 16 bh), 256 threads, TQ=2 queries/thread, K tiled in smem.
// ---------------------------------------------------------------------------
__global__ void __launch_bounds__(256) rowmax_kernel() {
    __shared__ float sK[512 * DH];   // 32 KB

    const int bh  = blockIdx.y;
    const int tid = threadIdx.x;
    const float* Qb = g_Q + (size_t)bh * L * DH;
    const float* Kb = g_K + (size_t)bh * L * DH;

    const int q0 = blockIdx.x * 512 + tid;
    const int q1 = q0 + 256;

    const float4* qp0 = (const float4*)(Qb + (size_t)q0 * DH);
    const float4* qp1 = (const float4*)(Qb + (size_t)q1 * DH);
    float4 a0 = qp0[0], a1 = qp0[1], a2 = qp0[2], a3 = qp0[3];
    float4 b0 = qp1[0], b1 = qp1[1], b2 = qp1[2], b3 = qp1[3];

    float mx0 = -1e30f, mx1 = -1e30f;

    for (int ch = 0; ch < 8; ch++) {
        const float4* src = (const float4*)(Kb + (size_t)ch * 512 * DH);
        float4* dst = (float4*)sK;
#pragma unroll
        for (int i = tid; i < 2048; i += 256) dst[i] = src[i];
        __syncthreads();

        for (int k = 0; k < 512; k++) {
            const float4* kp = (const float4*)(sK + k * DH);
            float4 k0 = kp[0], k1 = kp[1], k2 = kp[2], k3 = kp[3];
            float d0 = dot16(a0, a1, a2, a3, k0, k1, k2, k3);
            float d1 = dot16(b0, b1, b2, b3, k0, k1, k2, k3);
            mx0 = fmaxf(mx0, d0);
            mx1 = fmaxf(mx1, d1);
        }
        __syncthreads();
    }
    g_m[bh * L + q0] = mx0 * 0.25f;
    g_m[bh * L + q1] = mx1 * 0.25f;
}

// ---------------------------------------------------------------------------
// Pass B: mean_attn[bh][k] = sum_q exp(0.25*(q.k) - m_q)   (1/L scale omitted;
// ranking-invariant). Thread owns keys -> local accumulation, no atomics.
// grid (8 k-tiles, 16 bh), 256 threads, TK=2 keys/thread, Q+m tiled in smem.
// ---------------------------------------------------------------------------
__global__ void __launch_bounds__(256) keysum_kernel() {
    __shared__ float sQ[512 * DH];   // 32 KB
    __shared__ float sM[512];

    const int bh  = blockIdx.y;
    const int tid = threadIdx.x;
    const float* Qb = g_Q + (size_t)bh * L * DH;
    const float* Kb = g_K + (size_t)bh * L * DH;

    const int k0 = blockIdx.x * 512 + tid;
    const int k1 = k0 + 256;

    const float4* kp0 = (const float4*)(Kb + (size_t)k0 * DH);
    const float4* kp1 = (const float4*)(Kb + (size_t)k1 * DH);
    float4 a0 = kp0[0], a1 = kp0[1], a2 = kp0[2], a3 = kp0[3];
    float4 b0 = kp1[0], b1 = kp1[1], b2 = kp1[2], b3 = kp1[3];

    float acc0 = 0.0f, acc1 = 0.0f;
    const float C1 = 0.25f * LOG2E;

    for (int ch = 0; ch < 8; ch++) {
        const float4* src = (const float4*)(Qb + (size_t)ch * 512 * DH);
        float4* dst = (float4*)sQ;
#pragma unroll
        for (int i = tid; i < 2048; i += 256) dst[i] = src[i];
#pragma unroll
        for (int i = tid; i < 512; i += 256)
            sM[i] = g_m[bh * L + ch * 512 + i] * LOG2E;
        __syncthreads();

        for (int q = 0; q < 512; q++) {
            const float4* qp = (const float4*)(sQ + q * DH);
            float4 q0 = qp[0], q1 = qp[1], q2 = qp[2], q3 = qp[3];
            float mq = sM[q];
            float d0 = dot16(a0, a1, a2, a3, q0, q1, q2, q3);
            float d1 = dot16(b0, b1, b2, b3, q0, q1, q2, q3);
            acc0 += ex2f(fmaf(d0, C1, -mq));
            acc1 += ex2f(fmaf(d1, C1, -mq));
        }
        __syncthreads();
    }
    g_mean[bh * L + k0] = acc0;
    g_mean[bh * L + k1] = acc1;
}

// ---------------------------------------------------------------------------
// Top-41 per (b,h). Iterative argmax; lowest index wins ties (top_k stable).
// ---------------------------------------------------------------------------
__global__ void __launch_bounds__(256) topk_kernel() {
    __shared__ float sv[L];          // 16 KB
    __shared__ float rv[256];
    __shared__ int   ri[256];

    const int bh  = blockIdx.x;
    const int tid = threadIdx.x;

    for (int i = tid; i < L; i += 256) sv[i] = g_mean[bh * L + i];
    __syncthreads();

    for (int r = 0; r < SK; r++) {
        float bv = -1e38f;
        int   bi = 0;
        for (int i = tid; i < L; i += 256) {   // ascending: strict > keeps lowest idx
            float v = sv[i];
            if (v > bv) { bv = v; bi = i; }
        }
        rv[tid] = bv;
        ri[tid] = bi;
        __syncthreads();
        for (int s = 128; s > 0; s >>= 1) {
            if (tid < s) {
                float v = rv[tid + s];
                int  ix = ri[tid + s];
                if (v > rv[tid] || (v == rv[tid] && ix < ri[tid])) {
                    rv[tid] = v;
                    ri[tid] = ix;
                }
            }
            __syncthreads();
        }
        if (tid == 0) {
            g_idx[bh * SK + r] = ri[0];
            sv[ri[0]] = -1e38f;
        }
        __syncthreads();
    }
}

// ---------------------------------------------------------------------------
// Sparse attention: softmax(Q . Ks^T * 0.25) @ Vs, 41 sampled keys.
// grid (16 q-chunks, 16 bh), one query per thread.
// ---------------------------------------------------------------------------
__global__ void __launch_bounds__(256) sparse_attn_kernel() {
    __shared__ float sKs[SK * DH];
    __shared__ float sVs[SK * DH];

    const int bh  = blockIdx.y;
    const int tid = threadIdx.x;
    const float* Qb = g_Q + (size_t)bh * L * DH;
    const float* Kb = g_K + (size_t)bh * L * DH;
    const float* Vb = g_V + (size_t)bh * L * DH;

    for (int i = tid; i < SK * DH; i += 256) {
        int s = i >> 4, d = i & 15;
        int kk = g_idx[bh * SK + s];
        sKs[i] = Kb[(size_t)kk * DH + d];
        sVs[i] = Vb[(size_t)kk * DH + d];
    }
    __syncthreads();

    const int q = blockIdx.x * 256 + tid;
    const float4* qp = (const float4*)(Qb + (size_t)q * DH);
    float4 a0 = qp[0], a1 = qp[1], a2 = qp[2], a3 = qp[3];

    float sc[SK];
    float mx = -1e30f;
#pragma unroll
    for (int s = 0; s < SK; s++) {
        const float4* kp = (const float4*)(sKs + s * DH);
        float d = dot16(a0, a1, a2, a3, kp[0], kp[1], kp[2], kp[3]);
        sc[s] = d;
        mx = fmaxf(mx, d);
    }

    const float C1 = 0.25f * LOG2E;
    float sum = 0.0f;
    float4 o0 = {0, 0, 0, 0}, o1 = {0, 0, 0, 0}, o2 = {0, 0, 0, 0}, o3 = {0, 0, 0, 0};
#pragma unroll
    for (int s = 0; s < SK; s++) {
        float w = ex2f((sc[s] - mx) * C1);
        sum += w;
        const float4* vp = (const float4*)(sVs + s * DH);
        float4 v0 = vp[0], v1 = vp[1], v2 = vp[2], v3 = vp[3];
        o0.x = fmaf(w, v0.x, o0.x); o0.y = fmaf(w, v0.y, o0.y);
        o0.z = fmaf(w, v0.z, o0.z); o0.w = fmaf(w, v0.w, o0.w);
        o1.x = fmaf(w, v1.x, o1.x); o1.y = fmaf(w, v1.y, o1.y);
        o1.z = fmaf(w, v1.z, o1.z); o1.w = fmaf(w, v1.w, o1.w);
        o2.x = fmaf(w, v2.x, o2.x); o2.y = fmaf(w, v2.y, o2.y);
        o2.z = fmaf(w, v2.z, o2.z); o2.w = fmaf(w, v2.w, o2.w);
        o3.x = fmaf(w, v3.x, o3.x); o3.y = fmaf(w, v3.y, o3.y);
        o3.z = fmaf(w, v3.z, o3.z); o3.w = fmaf(w, v3.w, o3.w);
    }
    float inv = 1.0f / sum;

    const int b = bh >> 3;
    const int h = bh & 7;
    float* op = g_ctx + ((size_t)b * L + q) * DM + h * DH;
    *(float4*)(op + 0)  = make_float4(o0.x * inv, o0.y * inv, o0.z * inv, o0.w * inv);
    *(float4*)(op + 4)  = make_float4(o1.x * inv, o1.y * inv, o1.z * inv, o1.w * inv);
    *(float4*)(op + 8)  = make_float4(o2.x * inv, o2.y * inv, o2.z * inv, o2.w * inv);
    *(float4*)(op + 12) = make_float4(o3.x * inv, o3.y * inv, o3.z * inv, o3.w * inv);
}

// ---------------------------------------------------------------------------
extern "C" void kernel_launch(void* const* d_in, const int* in_sizes, int n_in,
                              void* d_out, int out_size) {
    const float* x  = (const float*)d_in[0];
    const float* Wq = (const float*)d_in[1];
    const float* bq = (const float*)d_in[2];
    const float* Wk = (const float*)d_in[3];
    const float* bk = (const float*)d_in[4];
    const float* Wv = (const float*)d_in[5];
    const float* bv = (const float*)d_in[6];
    const float* Wo = (const float*)d_in[7];
    const float* bo = (const float*)d_in[8];

    qkv_gemm_kernel<<<dim3(128, 3), 256>>>(x, Wq, bq, Wk, bk, Wv, bv);
    rowmax_kernel<<<dim3(8, NBH), 256>>>();
    keysum_kernel<<<dim3(8, NBH), 256>>>();
    topk_kernel<<<NBH, 256>>>();
    sparse_attn_kernel<<<dim3(16, NBH), 256>>>();
    out_gemm_kernel<<<128, 256>>>(Wo, bo, (float*)d_out);
}

// round 6
// speedup vs baseline: 2.4455x; 2.4455x over previous
#include <cuda_runtime.h>
#include <cuda_fp16.h>
#include <cstdint>

// ---------------------------------------------------------------------------
// ProbSparseAttention  B=2, L=4096, dm=128, H=8, D=16, sample_k=41
// Score passes use split-fp16 (hi+lo) tensor-core MMA: s = qh*kh + qh*kl + ql*kh
// -> ~1e-7 relative accuracy (ql*kl term ~2^-22 dropped). Output path exact fp32.
// ---------------------------------------------------------------------------

#define L      4096
#define DM     128
#define H      8
#define DH     16
#define NBH    16          // B*H
#define SK     41          // sample_k = int(log(4096)*5)
#define LOG2E  1.4426950408889634f
#define C1     (0.25f * LOG2E)      // scale * log2(e)

// Scratch (device globals; no allocation allowed)
__device__ float  g_Q[NBH * L * DH];
__device__ float  g_K[NBH * L * DH];
__device__ float  g_V[NBH * L * DH];
__device__ __half g_Qh[NBH * L * DH];   // hi part of Q
__device__ __half g_Ql[NBH * L * DH];   // lo part of Q
__device__ __half g_Kh[NBH * L * DH];   // hi part of K
__device__ __half g_Kl[NBH * L * DH];   // lo part of K
__device__ float  g_ml[NBH * L];        // per-query  max(score)*LOG2E
__device__ float  g_mean[NBH * L];      // per-key sum of exp (1/L scale omitted)
__device__ int    g_idx[NBH * SK];
__device__ float  g_ctx[2 * L * DM];    // attention output, [B,L,H*D]

__device__ __forceinline__ float ex2f(float x) {
    float r;
    asm("ex2.approx.ftz.f32 %0, %1;" : "=f"(r) : "f"(x));
    return r;
}

__device__ __forceinline__ uint32_t smem_u32(const void* p) {
    return (uint32_t)__cvta_generic_to_shared(p);
}

// ldmatrix x4: four 8x8 fp16 tiles
__device__ __forceinline__ void ldsm4(uint32_t r[4], uint32_t addr) {
    asm volatile("ldmatrix.sync.aligned.m8n8.x4.shared.b16 {%0,%1,%2,%3}, [%4];"
                 : "=r"(r[0]), "=r"(r[1]), "=r"(r[2]), "=r"(r[3]) : "r"(addr));
}

// D = A(16x16) * B(16x8), zero C
__device__ __forceinline__ void mma_z(float c[4], const uint32_t a[4],
                                      uint32_t b0, uint32_t b1) {
    asm volatile(
        "mma.sync.aligned.m16n8k16.row.col.f32.f16.f16.f32 "
        "{%0,%1,%2,%3}, {%4,%5,%6,%7}, {%8,%9}, {%10,%11,%12,%13};"
        : "=f"(c[0]), "=f"(c[1]), "=f"(c[2]), "=f"(c[3])
        : "r"(a[0]), "r"(a[1]), "r"(a[2]), "r"(a[3]),
          "r"(b0), "r"(b1),
          "f"(0.0f), "f"(0.0f), "f"(0.0f), "f"(0.0f));
}

// C += A * B (accumulating)
__device__ __forceinline__ void mma_acc(float c[4], const uint32_t a[4],
                                        uint32_t b0, uint32_t b1) {
    asm volatile(
        "mma.sync.aligned.m16n8k16.row.col.f32.f16.f16.f32 "
        "{%0,%1,%2,%3}, {%4,%5,%6,%7}, {%8,%9}, {%0,%1,%2,%3};"
        : "+f"(c[0]), "+f"(c[1]), "+f"(c[2]), "+f"(c[3])
        : "r"(a[0]), "r"(a[1]), "r"(a[2]), "r"(a[3]),
          "r"(b0), "r"(b1));
}

__device__ __forceinline__ float dot16(const float4 a0, const float4 a1,
                                       const float4 a2, const float4 a3,
                                       const float4 b0, const float4 b1,
                                       const float4 b2, const float4 b3) {
    float s0 = a0.x * b0.x; s0 = fmaf(a0.y, b0.y, s0); s0 = fmaf(a0.z, b0.z, s0); s0 = fmaf(a0.w, b0.w, s0);
    float s1 = a1.x * b1.x; s1 = fmaf(a1.y, b1.y, s1); s1 = fmaf(a1.z, b1.z, s1); s1 = fmaf(a1.w, b1.w, s1);
    float s2 = a2.x * b2.x; s2 = fmaf(a2.y, b2.y, s2); s2 = fmaf(a2.z, b2.z, s2); s2 = fmaf(a2.w, b2.w, s2);
    float s3 = a3.x * b3.x; s3 = fmaf(a3.y, b3.y, s3); s3 = fmaf(a3.z, b3.z, s3); s3 = fmaf(a3.w, b3.w, s3);
    return (s0 + s1) + (s2 + s3);
}

// ---------------------------------------------------------------------------
// GEMM: C[8192,128] = A[8192,128] @ W[128,128] + bias
// HEADMAJOR also emits split-fp16 (hi, lo) copies for the score passes.
// ---------------------------------------------------------------------------
template <bool HEADMAJOR>
__device__ __forceinline__ void gemm_body(const float* __restrict__ A,
                                          const float* __restrict__ W,
                                          const float* __restrict__ bias,
                                          float* __restrict__ C,
                                          __half* __restrict__ Chi,
                                          __half* __restrict__ Clo) {
    __shared__ float sA[64][33];
    __shared__ float sW[32][128];

    const int tid = threadIdx.x;
    const int tx = tid & 15;
    const int ty = tid >> 4;
    const int rowBase = blockIdx.x * 64;

    float acc[4][8];
#pragma unroll
    for (int r = 0; r < 4; r++)
#pragma unroll
        for (int c = 0; c < 8; c++) acc[r][c] = 0.0f;

    for (int kc = 0; kc < 128; kc += 32) {
#pragma unroll
        for (int i = tid; i < 512; i += 256) {
            int r  = i >> 3;
            int c4 = i & 7;
            float4 v = *(const float4*)(A + (size_t)(rowBase + r) * DM + kc + c4 * 4);
            sA[r][c4 * 4 + 0] = v.x;
            sA[r][c4 * 4 + 1] = v.y;
            sA[r][c4 * 4 + 2] = v.z;
            sA[r][c4 * 4 + 3] = v.w;
        }
#pragma unroll
        for (int i = tid; i < 1024; i += 256) {
            int r  = i >> 5;
            int c4 = i & 31;
            *(float4*)(&sW[r][c4 * 4]) =
                *(const float4*)(W + (size_t)(kc + r) * DM + c4 * 4);
        }
        __syncthreads();

#pragma unroll
        for (int k = 0; k < 32; k++) {
            float a[4], b[8];
#pragma unroll
            for (int r = 0; r < 4; r++) a[r] = sA[ty * 4 + r][k];
#pragma unroll
            for (int c = 0; c < 8; c++) b[c] = sW[k][tx + 16 * c];
#pragma unroll
            for (int r = 0; r < 4; r++)
#pragma unroll
                for (int c = 0; c < 8; c++) acc[r][c] = fmaf(a[r], b[c], acc[r][c]);
        }
        __syncthreads();
    }

#pragma unroll
    for (int r = 0; r < 4; r++) {
        int row = rowBase + ty * 4 + r;
#pragma unroll
        for (int c = 0; c < 8; c++) {
            int col = tx + 16 * c;
            float val = acc[r][c] + bias[col];
            if (HEADMAJOR) {
                int b  = row >> 12;
                int l  = row & (L - 1);
                int h  = col >> 4;
                int d  = col & 15;
                size_t o = ((size_t)(b * H + h) * L + l) * DH + d;
                C[o] = val;
                if (Chi) {
                    __half hi = __float2half_rn(val);
                    Chi[o] = hi;
                    Clo[o] = __float2half_rn(val - __half2float(hi));
                }
            } else {
                C[(size_t)row * DM + col] = val;
            }
        }
    }
}

__global__ void __launch_bounds__(256)
qkv_gemm_kernel(const float* __restrict__ x,
                const float* __restrict__ Wq, const float* __restrict__ bq,
                const float* __restrict__ Wk, const float* __restrict__ bk,
                const float* __restrict__ Wv, const float* __restrict__ bv) {
    int which = blockIdx.y;
    const float* W    = (which == 0) ? Wq : (which == 1) ? Wk : Wv;
    const float* bias = (which == 0) ? bq : (which == 1) ? bk : bv;
    float* out        = (which == 0) ? g_Q : (which == 1) ? g_K : g_V;
    __half* ohi       = (which == 0) ? g_Qh : (which == 1) ? g_Kh : (__half*)0;
    __half* olo       = (which == 0) ? g_Ql : (which == 1) ? g_Kl : (__half*)0;
    gemm_body<true>(x, W, bias, out, ohi, olo);
}

__global__ void __launch_bounds__(256)
out_gemm_kernel(const float* __restrict__ Wo, const float* __restrict__ bo,
                float* __restrict__ out) {
    gemm_body<false>(g_ctx, Wo, bo, out, (__half*)0, (__half*)0);
}

// ---------------------------------------------------------------------------
// Pass A (split MMA): g_ml[q] = max_k(q.k) * 0.25 * LOG2E
// Block = (bh, 128 queries): 8 warps x 16 queries. K hi/lo staged 256/chunk in
// smem (rows padded to 24 halves = 48B, conflict-free ldmatrix partition).
// ---------------------------------------------------------------------------
__global__ void __launch_bounds__(256) rowmax_mma_kernel() {
    __shared__ __align__(16) __half sKh[256 * 24];   // 12 KB
    __shared__ __align__(16) __half sKl[256 * 24];   // 12 KB

    const int bh = blockIdx.y, tid = threadIdx.x;
    const int warp = tid >> 5, lane = tid & 31;
    const int g = lane >> 2, tg = lane & 3;
    const __half* Qhp = g_Qh + (size_t)bh * L * DH;
    const __half* Qlp = g_Ql + (size_t)bh * L * DH;
    const __half* Khp = g_Kh + (size_t)bh * L * DH;
    const __half* Klp = g_Kl + (size_t)bh * L * DH;

    const int q0 = blockIdx.x * 128 + warp * 16 + g;

    uint32_t ah[4], al[4];
    ah[0] = *(const uint32_t*)(Qhp + (size_t)q0 * 16 + tg * 2);
    ah[1] = *(const uint32_t*)(Qhp + (size_t)(q0 + 8) * 16 + tg * 2);
    ah[2] = *(const uint32_t*)(Qhp + (size_t)q0 * 16 + tg * 2 + 8);
    ah[3] = *(const uint32_t*)(Qhp + (size_t)(q0 + 8) * 16 + tg * 2 + 8);
    al[0] = *(const uint32_t*)(Qlp + (size_t)q0 * 16 + tg * 2);
    al[1] = *(const uint32_t*)(Qlp + (size_t)(q0 + 8) * 16 + tg * 2);
    al[2] = *(const uint32_t*)(Qlp + (size_t)q0 * 16 + tg * 2 + 8);
    al[3] = *(const uint32_t*)(Qlp + (size_t)(q0 + 8) * 16 + tg * 2 + 8);

    float mx0 = -1e30f, mx1 = -1e30f;

    // ldmatrix B partition: m0=rows0-7/d0-7, m1=rows0-7/d8-15, m2=rows8-15/d0-7, m3=rows8-15/d8-15
    const int lrow = (lane & 7) + ((lane >> 4) << 3);
    const int lcol = (lane & 8);

    for (int ch = 0; ch < 16; ch++) {
#pragma unroll
        for (int i = tid; i < 512; i += 256) {
            int row = i >> 1, h8 = (i & 1) * 8;
            *(uint4*)(sKh + row * 24 + h8) =
                *(const uint4*)(Khp + (size_t)(ch * 256 + row) * 16 + h8);
            *(uint4*)(sKl + row * 24 + h8) =
                *(const uint4*)(Klp + (size_t)(ch * 256 + row) * 16 + h8);
        }
        __syncthreads();

        uint32_t baseh = smem_u32(sKh + lrow * 24 + lcol);
        uint32_t basel = smem_u32(sKl + lrow * 24 + lcol);
#pragma unroll 2
        for (int kb = 0; kb < 256; kb += 16) {
            uint32_t rh[4], rl[4];
            ldsm4(rh, baseh + kb * 48);
            ldsm4(rl, basel + kb * 48);

            float c[4], cx[4];
            // keys 0-7 of this block
            mma_z(c, ah, rh[0], rh[1]);
            mma_z(cx, ah, rl[0], rl[1]);
            mma_acc(cx, al, rh[0], rh[1]);
            mx0 = fmaxf(mx0, fmaxf(c[0] + cx[0], c[1] + cx[1]));
            mx1 = fmaxf(mx1, fmaxf(c[2] + cx[2], c[3] + cx[3]));
            // keys 8-15
            mma_z(c, ah, rh[2], rh[3]);
            mma_z(cx, ah, rl[2], rl[3]);
            mma_acc(cx, al, rh[2], rh[3]);
            mx0 = fmaxf(mx0, fmaxf(c[0] + cx[0], c[1] + cx[1]));
            mx1 = fmaxf(mx1, fmaxf(c[2] + cx[2], c[3] + cx[3]));
        }
        __syncthreads();
    }

    mx0 = fmaxf(mx0, __shfl_xor_sync(0xffffffffu, mx0, 1));
    mx0 = fmaxf(mx0, __shfl_xor_sync(0xffffffffu, mx0, 2));
    mx1 = fmaxf(mx1, __shfl_xor_sync(0xffffffffu, mx1, 1));
    mx1 = fmaxf(mx1, __shfl_xor_sync(0xffffffffu, mx1, 2));
    if (tg == 0) {
        g_ml[bh * L + q0]     = mx0 * C1;
        g_ml[bh * L + q0 + 8] = mx1 * C1;
    }
}

// ---------------------------------------------------------------------------
// Pass B (split MMA): g_mean[k] = sum_q exp2(score*C1 - ml[q])
// Block = (bh, 64 keys): warp owns 8 keys (hi/lo B-frags in regs), loops queries.
// ---------------------------------------------------------------------------
__global__ void __launch_bounds__(256) keysum_mma_kernel() {
    __shared__ __align__(16) __half sQh[256 * 24];   // 12 KB
    __shared__ __align__(16) __half sQl[256 * 24];   // 12 KB
    __shared__ float sM[256];

    const int bh = blockIdx.y, tid = threadIdx.x;
    const int warp = tid >> 5, lane = tid & 31;
    const int g = lane >> 2, tg = lane & 3;
    const __half* Qhp = g_Qh + (size_t)bh * L * DH;
    const __half* Qlp = g_Ql + (size_t)bh * L * DH;
    const __half* Khp = g_Kh + (size_t)bh * L * DH;
    const __half* Klp = g_Kl + (size_t)bh * L * DH;

    const int kbase = blockIdx.x * 64 + warp * 8;

    uint32_t bh0 = *(const uint32_t*)(Khp + (size_t)(kbase + g) * 16 + tg * 2);
    uint32_t bh1 = *(const uint32_t*)(Khp + (size_t)(kbase + g) * 16 + tg * 2 + 8);
    uint32_t bl0 = *(const uint32_t*)(Klp + (size_t)(kbase + g) * 16 + tg * 2);
    uint32_t bl1 = *(const uint32_t*)(Klp + (size_t)(kbase + g) * 16 + tg * 2 + 8);

    float kacc0 = 0.0f, kacc1 = 0.0f;

    // ldmatrix A partition: m0=rows0-7/d0-7, m1=rows8-15/d0-7, m2=rows0-7/d8-15, m3=rows8-15/d8-15
    const int mi = lane >> 3;
    const int lrow = (lane & 7) + ((mi & 1) << 3);
    const int lcol = (mi >> 1) << 3;

    for (int ch = 0; ch < 16; ch++) {
#pragma unroll
        for (int i = tid; i < 512; i += 256) {
            int row = i >> 1, h8 = (i & 1) * 8;
            *(uint4*)(sQh + row * 24 + h8) =
                *(const uint4*)(Qhp + (size_t)(ch * 256 + row) * 16 + h8);
            *(uint4*)(sQl + row * 24 + h8) =
                *(const uint4*)(Qlp + (size_t)(ch * 256 + row) * 16 + h8);
        }
        if (tid < 256) sM[tid] = g_ml[bh * L + ch * 256 + tid];
        __syncthreads();

        uint32_t baseh = smem_u32(sQh + lrow * 24 + lcol);
        uint32_t basel = smem_u32(sQl + lrow * 24 + lcol);
#pragma unroll 2
        for (int qb = 0; qb < 256; qb += 16) {
            uint32_t qah[4], qal[4];
            ldsm4(qah, baseh + qb * 48);
            ldsm4(qal, basel + qb * 48);

            float c[4], cx[4];
            mma_z(c, qah, bh0, bh1);
            mma_z(cx, qah, bl0, bl1);
            mma_acc(cx, qal, bh0, bh1);

            float ml0 = sM[qb + g], ml1 = sM[qb + g + 8];
            kacc0 += ex2f(fmaf(c[0] + cx[0], C1, -ml0)) + ex2f(fmaf(c[2] + cx[2], C1, -ml1));
            kacc1 += ex2f(fmaf(c[1] + cx[1], C1, -ml0)) + ex2f(fmaf(c[3] + cx[3], C1, -ml1));
        }
        __syncthreads();
    }

    kacc0 += __shfl_xor_sync(0xffffffffu, kacc0, 4);
    kacc0 += __shfl_xor_sync(0xffffffffu, kacc0, 8);
    kacc0 += __shfl_xor_sync(0xffffffffu, kacc0, 16);
    kacc1 += __shfl_xor_sync(0xffffffffu, kacc1, 4);
    kacc1 += __shfl_xor_sync(0xffffffffu, kacc1, 8);
    kacc1 += __shfl_xor_sync(0xffffffffu, kacc1, 16);
    if (g == 0) {
        g_mean[bh * L + kbase + tg * 2]     = kacc0;
        g_mean[bh * L + kbase + tg * 2 + 1] = kacc1;
    }
}

// ---------------------------------------------------------------------------
// Top-41 per (b,h): register-resident iterative argmax, lowest-index ties.
// ---------------------------------------------------------------------------
__global__ void __launch_bounds__(256) topk_kernel() {
    __shared__ float swv[8];
    __shared__ int   swi[8];
    __shared__ int   s_win;

    const int bh = blockIdx.x, tid = threadIdx.x;
    const int lane = tid & 31, warp = tid >> 5;

    float v[16];
#pragma unroll
    for (int j = 0; j < 16; j++) v[j] = g_mean[bh * L + (j << 8) + tid];

    for (int r = 0; r < SK; r++) {
        float bv = v[0];
        int bj = 0;
#pragma unroll
        for (int j = 1; j < 16; j++)
            if (v[j] > bv) { bv = v[j]; bj = j; }     // strict > keeps lowest idx
        int bi = (bj << 8) + tid;

#pragma unroll
        for (int s = 16; s > 0; s >>= 1) {
            float ov = __shfl_xor_sync(0xffffffffu, bv, s);
            int   oi = __shfl_xor_sync(0xffffffffu, bi, s);
            if (ov > bv || (ov == bv && oi < bi)) { bv = ov; bi = oi; }
        }
        if (lane == 0) { swv[warp] = bv; swi[warp] = bi; }
        __syncthreads();
        if (tid == 0) {
            float wv = swv[0]; int wi = swi[0];
#pragma unroll
            for (int w = 1; w < 8; w++) {
                if (swv[w] > wv || (swv[w] == wv && swi[w] < wi)) { wv = swv[w]; wi = swi[w]; }
            }
            g_idx[bh * SK + r] = wi;
            s_win = wi;
        }
        __syncthreads();
        int w = s_win;
        if ((w & 255) == tid) v[w >> 8] = -1e38f;
    }
}

// ---------------------------------------------------------------------------
// Sparse attention: softmax(Q . Ks^T * 0.25) @ Vs, 41 sampled keys (exact fp32)
// ---------------------------------------------------------------------------
__global__ void __launch_bounds__(256) sparse_attn_kernel() {
    __shared__ float sKs[SK * DH];
    __shared__ float sVs[SK * DH];

    const int bh = blockIdx.y, tid = threadIdx.x;
    const float* Qb = g_Q + (size_t)bh * L * DH;
    const float* Kb = g_K + (size_t)bh * L * DH;
    const float* Vb = g_V + (size_t)bh * L * DH;

    for (int i = tid; i < SK * DH; i += 256) {
        int s = i >> 4, d = i & 15;
        int kk = g_idx[bh * SK + s];
        sKs[i] = Kb[(size_t)kk * DH + d];
        sVs[i] = Vb[(size_t)kk * DH + d];
    }
    __syncthreads();

    const int q = blockIdx.x * 256 + tid;
    const float4* qp = (const float4*)(Qb + (size_t)q * DH);
    float4 a0 = qp[0], a1 = qp[1], a2 = qp[2], a3 = qp[3];

    float sc[SK];
    float mx = -1e30f;
#pragma unroll
    for (int s = 0; s < SK; s++) {
        const float4* kp = (const float4*)(sKs + s * DH);
        float d = dot16(a0, a1, a2, a3, kp[0], kp[1], kp[2], kp[3]);
        sc[s] = d;
        mx = fmaxf(mx, d);
    }

    float sum = 0.0f;
    float4 o0 = {0, 0, 0, 0}, o1 = {0, 0, 0, 0}, o2 = {0, 0, 0, 0}, o3 = {0, 0, 0, 0};
#pragma unroll
    for (int s = 0; s < SK; s++) {
        float w = ex2f((sc[s] - mx) * C1);
        sum += w;
        const float4* vp = (const float4*)(sVs + s * DH);
        float4 v0 = vp[0], v1 = vp[1], v2 = vp[2], v3 = vp[3];
        o0.x = fmaf(w, v0.x, o0.x); o0.y = fmaf(w, v0.y, o0.y);
        o0.z = fmaf(w, v0.z, o0.z); o0.w = fmaf(w, v0.w, o0.w);
        o1.x = fmaf(w, v1.x, o1.x); o1.y = fmaf(w, v1.y, o1.y);
        o1.z = fmaf(w, v1.z, o1.z); o1.w = fmaf(w, v1.w, o1.w);
        o2.x = fmaf(w, v2.x, o2.x); o2.y = fmaf(w, v2.y, o2.y);
        o2.z = fmaf(w, v2.z, o2.z); o2.w = fmaf(w, v2.w, o2.w);
        o3.x = fmaf(w, v3.x, o3.x); o3.y = fmaf(w, v3.y, o3.y);
        o3.z = fmaf(w, v3.z, o3.z); o3.w = fmaf(w, v3.w, o3.w);
    }
    float inv = 1.0f / sum;

    const int b = bh >> 3;
    const int h = bh & 7;
    float* op = g_ctx + ((size_t)b * L + q) * DM + h * DH;
    *(float4*)(op + 0)  = make_float4(o0.x * inv, o0.y * inv, o0.z * inv, o0.w * inv);
    *(float4*)(op + 4)  = make_float4(o1.x * inv, o1.y * inv, o1.z * inv, o1.w * inv);
    *(float4*)(op + 8)  = make_float4(o2.x * inv, o2.y * inv, o2.z * inv, o2.w * inv);
    *(float4*)(op + 12) = make_float4(o3.x * inv, o3.y * inv, o3.z * inv, o3.w * inv);
}

// ---------------------------------------------------------------------------
extern "C" void kernel_launch(void* const* d_in, const int* in_sizes, int n_in,
                              void* d_out, int out_size) {
    const float* x  = (const float*)d_in[0];
    const float* Wq = (const float*)d_in[1];
    const float* bq = (const float*)d_in[2];
    const float* Wk = (const float*)d_in[3];
    const float* bk = (const float*)d_in[4];
    const float* Wv = (const float*)d_in[5];
    const float* bv = (const float*)d_in[6];
    const float* Wo = (const float*)d_in[7];
    const float* bo = (const float*)d_in[8];

    qkv_gemm_kernel<<<dim3(128, 3), 256>>>(x, Wq, bq, Wk, bk, Wv, bv);
    rowmax_mma_kernel<<<dim3(32, NBH), 256>>>();
    keysum_mma_kernel<<<dim3(64, NBH), 256>>>();
    topk_kernel<<<NBH, 256>>>();
    sparse_attn_kernel<<<dim3(16, NBH), 256>>>();
    out_gemm_kernel<<<128, 256>>>(Wo, bo, (float*)d_out);
}

// round 8
// speedup vs baseline: 2.7009x; 1.1044x over previous
#include <cuda_runtime.h>
#include <cuda_fp16.h>
#include <cstdint>

// ---------------------------------------------------------------------------
// ProbSparseAttention  B=2, L=4096, dm=128, H=8, D=16, sample_k=41
// Score passes: split-fp16 (hi+lo) tensor-core MMA, cp.async double-buffered.
// Top-k: radix select. Output path exact fp32.
// ---------------------------------------------------------------------------

#define L      4096
#define DM     128
#define H      8
#define DH     16
#define NBH    16          // B*H
#define SK     41          // sample_k = int(log(4096)*5)
#define LOG2E  1.4426950408889634f
#define C1     (0.25f * LOG2E)      // scale * log2(e)
#define CHK    128         // rows per smem chunk in score passes
#define NCH    (L / CHK)   // 32 chunks

// Scratch (device globals; no allocation allowed)
__device__ float  g_Q[NBH * L * DH];
__device__ float  g_K[NBH * L * DH];
__device__ float  g_V[NBH * L * DH];
__device__ __half g_Qh[NBH * L * DH];   // hi part of Q
__device__ __half g_Ql[NBH * L * DH];   // lo part of Q
__device__ __half g_Kh[NBH * L * DH];   // hi part of K
__device__ __half g_Kl[NBH * L * DH];   // lo part of K
__device__ float  g_ml[NBH * L];        // per-query  max(score)*LOG2E
__device__ float  g_mean[NBH * L];      // per-key sum of exp (1/L scale omitted)
__device__ int    g_idx[NBH * SK];
__device__ float  g_ctx[2 * L * DM];    // attention output, [B,L,H*D]

__device__ __forceinline__ float ex2f(float x) {
    float r;
    asm("ex2.approx.ftz.f32 %0, %1;" : "=f"(r) : "f"(x));
    return r;
}

__device__ __forceinline__ uint32_t smem_u32(const void* p) {
    return (uint32_t)__cvta_generic_to_shared(p);
}

__device__ __forceinline__ void cpasync16(uint32_t saddr, const void* gptr) {
    asm volatile("cp.async.ca.shared.global [%0], [%1], 16;"
                 :: "r"(saddr), "l"(gptr));
}
__device__ __forceinline__ void cp_commit() {
    asm volatile("cp.async.commit_group;");
}
template <int N>
__device__ __forceinline__ void cp_wait() {
    asm volatile("cp.async.wait_group %0;" :: "n"(N));
}

// ldmatrix x4: four 8x8 fp16 tiles
__device__ __forceinline__ void ldsm4(uint32_t r[4], uint32_t addr) {
    asm volatile("ldmatrix.sync.aligned.m8n8.x4.shared.b16 {%0,%1,%2,%3}, [%4];"
                 : "=r"(r[0]), "=r"(r[1]), "=r"(r[2]), "=r"(r[3]) : "r"(addr));
}

// D = A(16x16) * B(16x8), zero C
__device__ __forceinline__ void mma_z(float c[4], const uint32_t a[4],
                                      uint32_t b0, uint32_t b1) {
    asm volatile(
        "mma.sync.aligned.m16n8k16.row.col.f32.f16.f16.f32 "
        "{%0,%1,%2,%3}, {%4,%5,%6,%7}, {%8,%9}, {%10,%11,%12,%13};"
        : "=f"(c[0]), "=f"(c[1]), "=f"(c[2]), "=f"(c[3])
        : "r"(a[0]), "r"(a[1]), "r"(a[2]), "r"(a[3]),
          "r"(b0), "r"(b1),
          "f"(0.0f), "f"(0.0f), "f"(0.0f), "f"(0.0f));
}

// C += A * B (accumulating)
__device__ __forceinline__ void mma_acc(float c[4], const uint32_t a[4],
                                        uint32_t b0, uint32_t b1) {
    asm volatile(
        "mma.sync.aligned.m16n8k16.row.col.f32.f16.f16.f32 "
        "{%0,%1,%2,%3}, {%4,%5,%6,%7}, {%8,%9}, {%0,%1,%2,%3};"
        : "+f"(c[0]), "+f"(c[1]), "+f"(c[2]), "+f"(c[3])
        : "r"(a[0]), "r"(a[1]), "r"(a[2]), "r"(a[3]),
          "r"(b0), "r"(b1));
}

__device__ __forceinline__ float dot16(const float4 a0, const float4 a1,
                                       const float4 a2, const float4 a3,
                                       const float4 b0, const float4 b1,
                                       const float4 b2, const float4 b3) {
    float s0 = a0.x * b0.x; s0 = fmaf(a0.y, b0.y, s0); s0 = fmaf(a0.z, b0.z, s0); s0 = fmaf(a0.w, b0.w, s0);
    float s1 = a1.x * b1.x; s1 = fmaf(a1.y, b1.y, s1); s1 = fmaf(a1.z, b1.z, s1); s1 = fmaf(a1.w, b1.w, s1);
    float s2 = a2.x * b2.x; s2 = fmaf(a2.y, b2.y, s2); s2 = fmaf(a2.z, b2.z, s2); s2 = fmaf(a2.w, b2.w, s2);
    float s3 = a3.x * b3.x; s3 = fmaf(a3.y, b3.y, s3); s3 = fmaf(a3.z, b3.z, s3); s3 = fmaf(a3.w, b3.w, s3);
    return (s0 + s1) + (s2 + s3);
}

// ---------------------------------------------------------------------------
// GEMM: C[8192,128] = A[8192,128] @ W[128,128] + bias
// HEADMAJOR also emits split-fp16 (hi, lo) copies for the score passes.
// ---------------------------------------------------------------------------
template <bool HEADMAJOR>
__device__ __forceinline__ void gemm_body(const float* __restrict__ A,
                                          const float* __restrict__ W,
                                          const float* __restrict__ bias,
                                          float* __restrict__ C,
                                          __half* __restrict__ Chi,
                                          __half* __restrict__ Clo) {
    __shared__ float sA[64][33];
    __shared__ float sW[32][128];

    const int tid = threadIdx.x;
    const int tx = tid & 15;
    const int ty = tid >> 4;
    const int rowBase = blockIdx.x * 64;

    float acc[4][8];
#pragma unroll
    for (int r = 0; r < 4; r++)
#pragma unroll
        for (int c = 0; c < 8; c++) acc[r][c] = 0.0f;

    for (int kc = 0; kc < 128; kc += 32) {
#pragma unroll
        for (int i = tid; i < 512; i += 256) {
            int r  = i >> 3;
            int c4 = i & 7;
            float4 v = *(const float4*)(A + (size_t)(rowBase + r) * DM + kc + c4 * 4);
            sA[r][c4 * 4 + 0] = v.x;
            sA[r][c4 * 4 + 1] = v.y;
            sA[r][c4 * 4 + 2] = v.z;
            sA[r][c4 * 4 + 3] = v.w;
        }
#pragma unroll
        for (int i = tid; i < 1024; i += 256) {
            int r  = i >> 5;
            int c4 = i & 31;
            *(float4*)(&sW[r][c4 * 4]) =
                *(const float4*)(W + (size_t)(kc + r) * DM + c4 * 4);
        }
        __syncthreads();

#pragma unroll
        for (int k = 0; k < 32; k++) {
            float a[4], b[8];
#pragma unroll
            for (int r = 0; r < 4; r++) a[r] = sA[ty * 4 + r][k];
#pragma unroll
            for (int c = 0; c < 8; c++) b[c] = sW[k][tx + 16 * c];
#pragma unroll
            for (int r = 0; r < 4; r++)
#pragma unroll
                for (int c = 0; c < 8; c++) acc[r][c] = fmaf(a[r], b[c], acc[r][c]);
        }
        __syncthreads();
    }

#pragma unroll
    for (int r = 0; r < 4; r++) {
        int row = rowBase + ty * 4 + r;
#pragma unroll
        for (int c = 0; c < 8; c++) {
            int col = tx + 16 * c;
            float val = acc[r][c] + bias[col];
            if (HEADMAJOR) {
                int b  = row >> 12;
                int l  = row & (L - 1);
                int h  = col >> 4;
                int d  = col & 15;
                size_t o = ((size_t)(b * H + h) * L + l) * DH + d;
                C[o] = val;
                if (Chi) {
                    __half hi = __float2half_rn(val);
                    Chi[o] = hi;
                    Clo[o] = __float2half_rn(val - __half2float(hi));
                }
            } else {
                C[(size_t)row * DM + col] = val;
            }
        }
    }
}

__global__ void __launch_bounds__(256)
qkv_gemm_kernel(const float* __restrict__ x,
                const float* __restrict__ Wq, const float* __restrict__ bq,
                const float* __restrict__ Wk, const float* __restrict__ bk,
                const float* __restrict__ Wv, const float* __restrict__ bv) {
    int which = blockIdx.y;
    const float* W    = (which == 0) ? Wq : (which == 1) ? Wk : Wv;
    const float* bias = (which == 0) ? bq : (which == 1) ? bk : bv;
    float* out        = (which == 0) ? g_Q : (which == 1) ? g_K : g_V;
    __half* ohi       = (which == 0) ? g_Qh : (which == 1) ? g_Kh : (__half*)0;
    __half* olo       = (which == 0) ? g_Ql : (which == 1) ? g_Kl : (__half*)0;
    gemm_body<true>(x, W, bias, out, ohi, olo);
}

__global__ void __launch_bounds__(256)
out_gemm_kernel(const float* __restrict__ Wo, const float* __restrict__ bo,
                float* __restrict__ out) {
    gemm_body<false>(g_ctx, Wo, bo, out, (__half*)0, (__half*)0);
}

// ---------------------------------------------------------------------------
// Pass A (split MMA, double-buffered): g_ml[q] = max_k(q.k) * 0.25 * LOG2E
// Block = (bh, 128 queries): 8 warps x 16 queries. K hi/lo staged CHK rows per
// chunk via cp.async (rows padded to 24 halves = 48B, conflict-free ldmatrix).
// ---------------------------------------------------------------------------
__global__ void __launch_bounds__(256) rowmax_mma_kernel() {
    __shared__ __align__(16) __half sKh[2][CHK * 24];   // 2 x 6 KB
    __shared__ __align__(16) __half sKl[2][CHK * 24];   // 2 x 6 KB

    const int bh = blockIdx.y, tid = threadIdx.x;
    const int warp = tid >> 5, lane = tid & 31;
    const int g = lane >> 2, tg = lane & 3;
    const __half* Qhp = g_Qh + (size_t)bh * L * DH;
    const __half* Qlp = g_Ql + (size_t)bh * L * DH;
    const __half* Khp = g_Kh + (size_t)bh * L * DH;
    const __half* Klp = g_Kl + (size_t)bh * L * DH;

    const int q0 = blockIdx.x * 128 + warp * 16 + g;

    uint32_t ah[4], al[4];
    ah[0] = *(const uint32_t*)(Qhp + (size_t)q0 * 16 + tg * 2);
    ah[1] = *(const uint32_t*)(Qhp + (size_t)(q0 + 8) * 16 + tg * 2);
    ah[2] = *(const uint32_t*)(Qhp + (size_t)q0 * 16 + tg * 2 + 8);
    ah[3] = *(const uint32_t*)(Qhp + (size_t)(q0 + 8) * 16 + tg * 2 + 8);
    al[0] = *(const uint32_t*)(Qlp + (size_t)q0 * 16 + tg * 2);
    al[1] = *(const uint32_t*)(Qlp + (size_t)(q0 + 8) * 16 + tg * 2);
    al[2] = *(const uint32_t*)(Qlp + (size_t)q0 * 16 + tg * 2 + 8);
    al[3] = *(const uint32_t*)(Qlp + (size_t)(q0 + 8) * 16 + tg * 2 + 8);

    float mx0 = -1e30f, mx1 = -1e30f;

    // ldmatrix B partition: m0=rows0-7/d0-7, m1=rows0-7/d8-15, m2=rows8-15/d0-7, m3=rows8-15/d8-15
    const int lrow = (lane & 7) + ((lane >> 4) << 3);
    const int lcol = (lane & 8);

    // 256 loads per array per chunk: 1 per thread
    auto load_chunk = [&](int buf, int ch) {
        int row = tid >> 1, h8 = (tid & 1) * 8;
        cpasync16(smem_u32(&sKh[buf][row * 24 + h8]),
                  Khp + (size_t)(ch * CHK + row) * 16 + h8);
        cpasync16(smem_u32(&sKl[buf][row * 24 + h8]),
                  Klp + (size_t)(ch * CHK + row) * 16 + h8);
    };

    load_chunk(0, 0);
    cp_commit();

    for (int ch = 0; ch < NCH; ch++) {
        int buf = ch & 1;
        if (ch + 1 < NCH) {
            load_chunk(buf ^ 1, ch + 1);
            cp_commit();
            cp_wait<1>();
        } else {
            cp_wait<0>();
        }
        __syncthreads();

        uint32_t baseh = smem_u32(&sKh[buf][lrow * 24 + lcol]);
        uint32_t basel = smem_u32(&sKl[buf][lrow * 24 + lcol]);
#pragma unroll
        for (int kb = 0; kb < CHK; kb += 16) {
            uint32_t rh[4], rl[4];
            ldsm4(rh, baseh + kb * 48);
            ldsm4(rl, basel + kb * 48);

            float c[4], cx[4];
            // keys 0-7 of this tile
            mma_z(c, ah, rh[0], rh[1]);
            mma_z(cx, ah, rl[0], rl[1]);
            mma_acc(cx, al, rh[0], rh[1]);
            mx0 = fmaxf(mx0, fmaxf(c[0] + cx[0], c[1] + cx[1]));
            mx1 = fmaxf(mx1, fmaxf(c[2] + cx[2], c[3] + cx[3]));
            // keys 8-15
            mma_z(c, ah, rh[2], rh[3]);
            mma_z(cx, ah, rl[2], rl[3]);
            mma_acc(cx, al, rh[2], rh[3]);
            mx0 = fmaxf(mx0, fmaxf(c[0] + cx[0], c[1] + cx[1]));
            mx1 = fmaxf(mx1, fmaxf(c[2] + cx[2], c[3] + cx[3]));
        }
        __syncthreads();
    }

    mx0 = fmaxf(mx0, __shfl_xor_sync(0xffffffffu, mx0, 1));
    mx0 = fmaxf(mx0, __shfl_xor_sync(0xffffffffu, mx0, 2));
    mx1 = fmaxf(mx1, __shfl_xor_sync(0xffffffffu, mx1, 1));
    mx1 = fmaxf(mx1, __shfl_xor_sync(0xffffffffu, mx1, 2));
    if (tg == 0) {
        g_ml[bh * L + q0]     = mx0 * C1;
        g_ml[bh * L + q0 + 8] = mx1 * C1;
    }
}

// ---------------------------------------------------------------------------
// Pass B (split MMA, double-buffered): g_mean[k] = sum_q exp2(score*C1 - ml[q])
// Block = (bh, 64 keys): warp owns 8 keys (hi/lo B-frags in regs), loops queries.
// ---------------------------------------------------------------------------
__global__ void __launch_bounds__(256) keysum_mma_kernel() {
    __shared__ __align__(16) __half sQh[2][CHK * 24];
    __shared__ __align__(16) __half sQl[2][CHK * 24];
    __shared__ __align__(16) float  sM[2][CHK];

    const int bh = blockIdx.y, tid = threadIdx.x;
    const int warp = tid >> 5, lane = tid & 31;
    const int g = lane >> 2, tg = lane & 3;
    const __half* Qhp = g_Qh + (size_t)bh * L * DH;
    const __half* Qlp = g_Ql + (size_t)bh * L * DH;
    const __half* Khp = g_Kh + (size_t)bh * L * DH;
    const __half* Klp = g_Kl + (size_t)bh * L * DH;
    const float*  Mlp = g_ml + (size_t)bh * L;

    const int kbase = blockIdx.x * 64 + warp * 8;

    uint32_t bh0 = *(const uint32_t*)(Khp + (size_t)(kbase + g) * 16 + tg * 2);
    uint32_t bh1 = *(const uint32_t*)(Khp + (size_t)(kbase + g) * 16 + tg * 2 + 8);
    uint32_t bl0 = *(const uint32_t*)(Klp + (size_t)(kbase + g) * 16 + tg * 2);
    uint32_t bl1 = *(const uint32_t*)(Klp + (size_t)(kbase + g) * 16 + tg * 2 + 8);

    float kacc0 = 0.0f, kacc1 = 0.0f;

    // ldmatrix A partition: m0=rows0-7/d0-7, m1=rows8-15/d0-7, m2=rows0-7/d8-15, m3=rows8-15/d8-15
    const int mi = lane >> 3;
    const int lrow = (lane & 7) + ((mi & 1) << 3);
    const int lcol = (mi >> 1) << 3;

    auto load_chunk = [&](int buf, int ch) {
        int row = tid >> 1, h8 = (tid & 1) * 8;
        cpasync16(smem_u32(&sQh[buf][row * 24 + h8]),
                  Qhp + (size_t)(ch * CHK + row) * 16 + h8);
        cpasync16(smem_u32(&sQl[buf][row * 24 + h8]),
                  Qlp + (size_t)(ch * CHK + row) * 16 + h8);
        if (tid < CHK / 4)
            cpasync16(smem_u32(&sM[buf][tid * 4]), Mlp + ch * CHK + tid * 4);
    };

    load_chunk(0, 0);
    cp_commit();

    for (int ch = 0; ch < NCH; ch++) {
        int buf = ch & 1;
        if (ch + 1 < NCH) {
            load_chunk(buf ^ 1, ch + 1);
            cp_commit();
            cp_wait<1>();
        } else {
            cp_wait<0>();
        }
        __syncthreads();

        uint32_t baseh = smem_u32(&sQh[buf][lrow * 24 + lcol]);
        uint32_t basel = smem_u32(&sQl[buf][lrow * 24 + lcol]);
#pragma unroll
        for (int qb = 0; qb < CHK; qb += 16) {
            uint32_t qah[4], qal[4];
            ldsm4(qah, baseh + qb * 48);
            ldsm4(qal, basel + qb * 48);

            float c[4], cx[4];
            mma_z(c, qah, bh0, bh1);
            mma_z(cx, qah, bl0, bl1);
            mma_acc(cx, qal, bh0, bh1);

            float ml0 = sM[buf][qb + g], ml1 = sM[buf][qb + g + 8];
            kacc0 += ex2f(fmaf(c[0] + cx[0], C1, -ml0)) + ex2f(fmaf(c[2] + cx[2], C1, -ml1));
            kacc1 += ex2f(fmaf(c[1] + cx[1], C1, -ml0)) + ex2f(fmaf(c[3] + cx[3], C1, -ml1));
        }
        __syncthreads();
    }

    kacc0 += __shfl_xor_sync(0xffffffffu, kacc0, 4);
    kacc0 += __shfl_xor_sync(0xffffffffu, kacc0, 8);
    kacc0 += __shfl_xor_sync(0xffffffffu, kacc0, 16);
    kacc1 += __shfl_xor_sync(0xffffffffu, kacc1, 4);
    kacc1 += __shfl_xor_sync(0xffffffffu, kacc1, 8);
    kacc1 += __shfl_xor_sync(0xffffffffu, kacc1, 16);
    if (g == 0) {
        g_mean[bh * L + kbase + tg * 2]     = kacc0;
        g_mean[bh * L + kbase + tg * 2 + 1] = kacc1;
    }
}

// ---------------------------------------------------------------------------
// Top-41 per (b,h): radix select (4x8-bit passes) for the threshold value,
// then emit all values > T plus lowest-index values == T (matches lax.top_k
// set semantics; output order irrelevant — gathered softmax is invariant).
// ---------------------------------------------------------------------------
__global__ void __launch_bounds__(256) topk_kernel() {
    __shared__ int hist[256];
    __shared__ int sfx[256];
    __shared__ uint32_t s_prefix;
    __shared__ int s_need;
    __shared__ int s_cnt, s_eqc;
    __shared__ int eq_idx[64];

    const int bh = blockIdx.x, tid = threadIdx.x;

    uint32_t u[16];
#pragma unroll
    for (int j = 0; j < 16; j++) {
        uint32_t b = __float_as_uint(g_mean[bh * L + (j << 8) + tid]);
        u[j] = (b & 0x80000000u) ? ~b : (b | 0x80000000u);   // orderable key
    }

    uint32_t prefix = 0;
    int need = SK;
#pragma unroll
    for (int pass = 0; pass < 4; pass++) {
        int sh = 24 - pass * 8;
        hist[tid] = 0;
        __syncthreads();
#pragma unroll
        for (int j = 0; j < 16; j++) {
            bool act = (pass == 0) || ((u[j] >> (sh + 8)) == prefix);
            if (act) atomicAdd(&hist[(u[j] >> sh) & 255], 1);
        }
        __syncthreads();
        // suffix sums over bins (descending-value cumulative count)
        sfx[tid] = hist[tid];
        __syncthreads();
        for (int off = 1; off < 256; off <<= 1) {
            int v = (tid + off < 256) ? sfx[tid + off] : 0;
            __syncthreads();
            sfx[tid] += v;
            __syncthreads();
        }
        int nxt = (tid < 255) ? sfx[tid + 1] : 0;
        if (sfx[tid] >= need && nxt < need) {
            s_prefix = (prefix << 8) | (uint32_t)tid;
            s_need = need - nxt;
        }
        __syncthreads();
        prefix = s_prefix;
        need = s_need;
        __syncthreads();
    }

    const uint32_t T = prefix;   // exact SK-th largest key
    if (tid == 0) { s_cnt = 0; s_eqc = 0; }
    __syncthreads();
#pragma unroll
    for (int j = 0; j < 16; j++) {
        if (u[j] > T) {
            int p = atomicAdd(&s_cnt, 1);
            g_idx[bh * SK + p] = (j << 8) + tid;
        } else if (u[j] == T) {
            int p = atomicAdd(&s_eqc, 1);
            if (p < 64) eq_idx[p] = (j << 8) + tid;
        }
    }
    __syncthreads();
    if (tid == 0) {
        int base = s_cnt;                 // == SK - need
        int m = s_eqc < 64 ? s_eqc : 64;
        for (int i = 1; i < m; i++) {     // insertion sort ascending (ties: lowest idx wins)
            int key = eq_idx[i], k2 = i - 1;
            while (k2 >= 0 && eq_idx[k2] > key) { eq_idx[k2 + 1] = eq_idx[k2]; k2--; }
            eq_idx[k2 + 1] = key;
        }
        for (int r = 0; r < need && r < m; r++)
            g_idx[bh * SK + base + r] = eq_idx[r];
    }
}

// ---------------------------------------------------------------------------
// Sparse attention: softmax(Q . Ks^T * 0.25) @ Vs, 41 sampled keys (exact fp32)
// ---------------------------------------------------------------------------
__global__ void __launch_bounds__(256) sparse_attn_kernel() {
    __shared__ float sKs[SK * DH];
    __shared__ float sVs[SK * DH];

    const int bh = blockIdx.y, tid = threadIdx.x;
    const float* Qb = g_Q + (size_t)bh * L * DH;
    const float* Kb = g_K + (size_t)bh * L * DH;
    const float* Vb = g_V + (size_t)bh * L * DH;

    for (int i = tid; i < SK * DH; i += 256) {
        int s = i >> 4, d = i & 15;
        int kk = g_idx[bh * SK + s];
        sKs[i] = Kb[(size_t)kk * DH + d];
        sVs[i] = Vb[(size_t)kk * DH + d];
    }
    __syncthreads();

    const int q = blockIdx.x * 256 + tid;
    const float4* qp = (const float4*)(Qb + (size_t)q * DH);
    float4 a0 = qp[0], a1 = qp[1], a2 = qp[2], a3 = qp[3];

    float sc[SK];
    float mx = -1e30f;
#pragma unroll
    for (int s = 0; s < SK; s++) {
        const float4* kp = (const float4*)(sKs + s * DH);
        float d = dot16(a0, a1, a2, a3, kp[0], kp[1], kp[2], kp[3]);
        sc[s] = d;
        mx = fmaxf(mx, d);
    }

    float sum = 0.0f;
    float4 o0 = {0, 0, 0, 0}, o1 = {0, 0, 0, 0}, o2 = {0, 0, 0, 0}, o3 = {0, 0, 0, 0};
#pragma unroll
    for (int s = 0; s < SK; s++) {
        float w = ex2f((sc[s] - mx) * C1);
        sum += w;
        const float4* vp = (const float4*)(sVs + s * DH);
        float4 v0 = vp[0], v1 = vp[1], v2 = vp[2], v3 = vp[3];
        o0.x = fmaf(w, v0.x, o0.x); o0.y = fmaf(w, v0.y, o0.y);
        o0.z = fmaf(w, v0.z, o0.z); o0.w = fmaf(w, v0.w, o0.w);
        o1.x = fmaf(w, v1.x, o1.x); o1.y = fmaf(w, v1.y, o1.y);
        o1.z = fmaf(w, v1.z, o1.z); o1.w = fmaf(w, v1.w, o1.w);
        o2.x = fmaf(w, v2.x, o2.x); o2.y = fmaf(w, v2.y, o2.y);
        o2.z = fmaf(w, v2.z, o2.z); o2.w = fmaf(w, v2.w, o2.w);
        o3.x = fmaf(w, v3.x, o3.x); o3.y = fmaf(w, v3.y, o3.y);
        o3.z = fmaf(w, v3.z, o3.z); o3.w = fmaf(w, v3.w, o3.w);
    }
    float inv = 1.0f / sum;

    const int b = bh >> 3;
    const int h = bh & 7;
    float* op = g_ctx + ((size_t)b * L + q) * DM + h * DH;
    *(float4*)(op + 0)  = make_float4(o0.x * inv, o0.y * inv, o0.z * inv, o0.w * inv);
    *(float4*)(op + 4)  = make_float4(o1.x * inv, o1.y * inv, o1.z * inv, o1.w * inv);
    *(float4*)(op + 8)  = make_float4(o2.x * inv, o2.y * inv, o2.z * inv, o2.w * inv);
    *(float4*)(op + 12) = make_float4(o3.x * inv, o3.y * inv, o3.z * inv, o3.w * inv);
}

// ---------------------------------------------------------------------------
extern "C" void kernel_launch(void* const* d_in, const int* in_sizes, int n_in,
                              void* d_out, int out_size) {
    const float* x  = (const float*)d_in[0];
    const float* Wq = (const float*)d_in[1];
    const float* bq = (const float*)d_in[2];
    const float* Wk = (const float*)d_in[3];
    const float* bk = (const float*)d_in[4];
    const float* Wv = (const float*)d_in[5];
    const float* bv = (const float*)d_in[6];
    const float* Wo = (const float*)d_in[7];
    const float* bo = (const float*)d_in[8];

    qkv_gemm_kernel<<<dim3(128, 3), 256>>>(x, Wq, bq, Wk, bk, Wv, bv);
    rowmax_mma_kernel<<<dim3(32, NBH), 256>>>();
    keysum_mma_kernel<<<dim3(64, NBH), 256>>>();
    topk_kernel<<<NBH, 256>>>();
    sparse_attn_kernel<<<dim3(16, NBH), 256>>>();
    out_gemm_kernel<<<128, 256>>>(Wo, bo, (float*)d_out);
}